// round 7
// baseline (speedup 1.0000x reference)
#include <cuda_runtime.h>
#include <math.h>

#define NB 512
#define SS 128
#define TT 128
#define EE 128
#define HH 1024
#define VV 128
#define G3 (3*HH)

// ---------------- device scratch (no allocation allowed) ----------------
__device__ float g_h[2][NB*HH];          // double-buffered hidden state
__device__ float g_Gsrc[VV*G3];          // token -> gi table (encoder)
__device__ float g_Gtrg[VV*G3];          // token -> gi table (decoder)
__device__ int   g_tok[NB];              // current decoder input tokens
__device__ float g_pred_part[8][NB*VV];  // split-K partials for pred GEMM

// ---------------- build gi lookup tables ----------------
// G[v][c] = (v==PAD? 0 : sum_e emb[v][e]*Wih[c][e]) + bih[c]
__global__ void build_tables(const float* __restrict__ emb_src,
                             const float* __restrict__ enc_Wih,
                             const float* __restrict__ enc_bih,
                             const float* __restrict__ emb_trg,
                             const float* __restrict__ dec_Wih,
                             const float* __restrict__ dec_bih)
{
    int idx = blockIdx.x * blockDim.x + threadIdx.x;   // 2*128*3072
    int which = idx / (VV*G3);
    int rem   = idx % (VV*G3);
    int v = rem / G3;
    int c = rem % G3;
    const float* emb = which ? emb_trg : emb_src;
    const float* W   = which ? dec_Wih : enc_Wih;
    const float* bi  = which ? dec_bih : enc_bih;
    float s = bi[c];
    if (v != 0) {  // PAD_IDX row of embedding is zeroed
        const float* e = emb + v*EE;
        const float* w = W + c*EE;
        #pragma unroll 8
        for (int k = 0; k < EE; k++) s += e[k]*w[k];
    }
    float* G = which ? g_Gtrg : g_Gsrc;
    G[v*G3 + c] = s;
}

// ---------------- init: h0 = 0, out[:,0,:] = 0, tok = trg[:,0] ----------------
__global__ void init_kernel(float* __restrict__ out, const int* __restrict__ trg)
{
    int i = blockIdx.x * blockDim.x + threadIdx.x;
    if (i < NB*HH) g_h[0][i] = 0.0f;
    if (i < NB*VV) {
        int b = i / VV, v = i % VV;
        out[b*(TT*VV) + v] = 0.0f;
    }
    if (i < NB) g_tok[i] = trg[i*TT];
}

// ---------------- fused GRU step: gh GEMM (3 gates) + gate math ----------------
// Arithmetic is bitwise-identical to the round-2 passing kernel: each output is
// one ascending-k FFMA chain; epilogue expressions verbatim. Only the tiling /
// grid changed (BN 64->32, 128-thread blocks, 256 blocks) for occupancy.
#define BM 64
#define BN 32     // h-columns per block (per gate)
#define BK 16
#define TM 8
#define TN 2
// blockDim = (16, 8) = 128 threads; grid = (HH/BN=32, NB/BM=8) = 256 blocks
// table_sel: 0 -> g_Gsrc (encoder), 1 -> g_Gtrg (decoder)
// ext_tok: device pointer to tokens (encoder: src+t, stride SS); nullptr -> g_tok
__global__ __launch_bounds__(128, 2)
void gru_step(int pin,
              const float* __restrict__ Whh, const float* __restrict__ bhh,
              int table_sel,
              const int* __restrict__ ext_tok, int tok_stride)
{
    const float* __restrict__ h_in = g_h[pin];
    float* __restrict__ h_out      = g_h[pin ^ 1];
    const float* __restrict__ G    = table_sel ? g_Gtrg : g_Gsrc;
    const int* __restrict__ tokp   = ext_tok ? ext_tok : g_tok;

    __shared__ float As[BK][BM+4];
    __shared__ float Bs[3][BK][BN+4];

    const int row0 = blockIdx.y * BM;
    const int col0 = blockIdx.x * BN;
    const int tx = threadIdx.x;          // 0..15
    const int ty = threadIdx.y;          // 0..7
    const int tid = ty*16 + tx;          // 0..127

    float acc[3][TM][TN];
    #pragma unroll
    for (int g = 0; g < 3; g++)
        #pragma unroll
        for (int i = 0; i < TM; i++)
            #pragma unroll
            for (int j = 0; j < TN; j++) acc[g][i][j] = 0.0f;

    const int bc = tid >> 2;             // B col 0..31
    const int bk = (tid & 3) << 2;       // B kvec*4

    for (int kt = 0; kt < HH; kt += BK) {
        // load A tile (h): 64 rows x 16 k, k-major in smem (2 float4 per thread)
        #pragma unroll
        for (int j = 0; j < 2; j++) {
            int v  = j*128 + tid;        // 0..255
            int ar = v >> 2;             // 0..63
            int ak = (v & 3) << 2;
            float4 av = *(const float4*)&h_in[(row0 + ar)*HH + kt + ak];
            As[ak+0][ar] = av.x; As[ak+1][ar] = av.y;
            As[ak+2][ar] = av.z; As[ak+3][ar] = av.w;
        }
        // load B tiles (Whh rows for 3 gates): 3 x 32 cols x 16 k (1 float4 each)
        #pragma unroll
        for (int g = 0; g < 3; g++) {
            float4 bv = *(const float4*)&Whh[(g*HH + col0 + bc)*HH + kt + bk];
            Bs[g][bk+0][bc] = bv.x; Bs[g][bk+1][bc] = bv.y;
            Bs[g][bk+2][bc] = bv.z; Bs[g][bk+3][bc] = bv.w;
        }
        __syncthreads();

        #pragma unroll
        for (int kk = 0; kk < BK; kk++) {
            float4 a0 = *(const float4*)&As[kk][ty*TM];
            float4 a1 = *(const float4*)&As[kk][ty*TM + 4];
            float a[TM] = {a0.x, a0.y, a0.z, a0.w, a1.x, a1.y, a1.z, a1.w};
            float b[3][TN];
            #pragma unroll
            for (int g = 0; g < 3; g++) {
                float2 bb = *(const float2*)&Bs[g][kk][tx*TN];
                b[g][0] = bb.x; b[g][1] = bb.y;
            }
            #pragma unroll
            for (int g = 0; g < 3; g++)
                #pragma unroll
                for (int i = 0; i < TM; i++)
                    #pragma unroll
                    for (int j = 0; j < TN; j++)
                        acc[g][i][j] += a[i] * b[g][j];
        }
        __syncthreads();
    }

    // fused gate epilogue (verbatim round-2)
    #pragma unroll
    for (int i = 0; i < TM; i++) {
        int row = row0 + ty*TM + i;
        int tk = tokp[row * tok_stride];
        const float* Grow = G + tk*G3;
        #pragma unroll
        for (int j = 0; j < TN; j++) {
            int col = col0 + tx*TN + j;
            float gr = acc[0][i][j] + bhh[col];
            float gz = acc[1][i][j] + bhh[HH + col];
            float gn = acc[2][i][j] + bhh[2*HH + col];
            float r = 1.0f / (1.0f + expf(-(Grow[col]        + gr)));
            float z = 1.0f / (1.0f + expf(-(Grow[HH + col]   + gz)));
            float n = tanhf(Grow[2*HH + col] + r * gn);
            float hp = h_in[row*HH + col];
            h_out[row*HH + col] = (1.0f - z)*n + z*hp;
        }
    }
}

// ---------------- decoder pred GEMM, split-K partials (verbatim round-2) -------
#define PBM 32
#define PBK 16
__global__ __launch_bounds__(256, 1)
void pred_part(int pcur, const float* __restrict__ fcW)
{
    const float* __restrict__ h = g_h[pcur];
    __shared__ float As[PBK][PBM+4];
    __shared__ float Bs[PBK][VV+4];

    const int row0 = blockIdx.x * PBM;
    const int k0   = blockIdx.y * (HH/8);     // 128-wide K chunk
    const int tx = threadIdx.x, ty = threadIdx.y;
    const int tid = ty*32 + tx;

    float acc[4][4];
    #pragma unroll
    for (int i = 0; i < 4; i++)
        #pragma unroll
        for (int j = 0; j < 4; j++) acc[i][j] = 0.0f;

    for (int kt = 0; kt < HH/8; kt += PBK) {
        if (tid < 128) {                     // A: 32 rows x 16 k = 128 float4
            int ar = tid >> 2;
            int ak = (tid & 3) << 2;
            float4 av = *(const float4*)&h[(row0+ar)*HH + k0 + kt + ak];
            As[ak+0][ar] = av.x; As[ak+1][ar] = av.y;
            As[ak+2][ar] = av.z; As[ak+3][ar] = av.w;
        }
        #pragma unroll
        for (int l = 0; l < 2; l++) {        // B: 128 cols x 16 k = 512 float4
            int t2 = l*256 + tid;
            int bc = t2 >> 2;
            int bk = (t2 & 3) << 2;
            float4 bv = *(const float4*)&fcW[bc*HH + k0 + kt + bk];
            Bs[bk+0][bc] = bv.x; Bs[bk+1][bc] = bv.y;
            Bs[bk+2][bc] = bv.z; Bs[bk+3][bc] = bv.w;
        }
        __syncthreads();
        #pragma unroll
        for (int kk = 0; kk < PBK; kk++) {
            float4 a = *(const float4*)&As[kk][ty*4];
            float4 b = *(const float4*)&Bs[kk][tx*4];
            float av[4] = {a.x,a.y,a.z,a.w};
            float bv[4] = {b.x,b.y,b.z,b.w};
            #pragma unroll
            for (int i = 0; i < 4; i++)
                #pragma unroll
                for (int j = 0; j < 4; j++) acc[i][j] += av[i]*bv[j];
        }
        __syncthreads();
    }
    float* dst = g_pred_part[blockIdx.y];
    #pragma unroll
    for (int i = 0; i < 4; i++)
        #pragma unroll
        for (int j = 0; j < 4; j++)
            dst[(row0 + ty*4 + i)*VV + tx*4 + j] = acc[i][j];
}

// ---------------- reduce partials, add bias, write out, argmax (verbatim R2) ---
__global__ void argmax_write(float* __restrict__ out,
                             const float* __restrict__ fcb,
                             const int* __restrict__ trg,
                             const void* __restrict__ tfr,
                             int t_out)
{
    int b = blockIdx.x;
    int v = threadIdx.x;
    float acc = fcb[v];
    #pragma unroll
    for (int p = 0; p < 8; p++) acc += g_pred_part[p][b*VV + v];
    out[b*(TT*VV) + t_out*VV + v] = acc;

    __shared__ float sval[128];
    __shared__ int   sidx[128];
    sval[v] = acc; sidx[v] = v;
    __syncthreads();
    for (int s = 64; s > 0; s >>= 1) {
        if (v < s) {
            // first-occurrence argmax (lowest index wins ties) like jnp.argmax
            if (sval[v+s] > sval[v] ||
                (sval[v+s] == sval[v] && sidx[v+s] < sidx[v])) {
                sval[v] = sval[v+s]; sidx[v] = sidx[v+s];
            }
        }
        __syncthreads();
    }
    if (v == 0) {
        int   ti  = ((const int*)tfr)[0];
        float tfv = ((const float*)tfr)[0];
        bool tf = (ti > 0) || (tfv > 0.0f);
        g_tok[b] = tf ? trg[b*TT + t_out] : sidx[0];
    }
}

// ---------------- host ----------------
extern "C" void kernel_launch(void* const* d_in, const int* in_sizes, int n_in,
                              void* d_out, int out_size)
{
    const int*   src     = (const int*)  d_in[0];
    const int*   trg     = (const int*)  d_in[1];
    const float* emb_src = (const float*)d_in[2];
    const float* emb_trg = (const float*)d_in[3];
    const float* enc_Wih = (const float*)d_in[4];
    const float* enc_Whh = (const float*)d_in[5];
    const float* enc_bih = (const float*)d_in[6];
    const float* enc_bhh = (const float*)d_in[7];
    const float* dec_Wih = (const float*)d_in[8];
    const float* dec_Whh = (const float*)d_in[9];
    const float* dec_bih = (const float*)d_in[10];
    const float* dec_bhh = (const float*)d_in[11];
    const float* fc_W    = (const float*)d_in[12];
    const float* fc_b    = (const float*)d_in[13];
    const void*  tfr     =               d_in[14];
    float* out = (float*)d_out;

    build_tables<<<(2*VV*G3)/256, 256>>>(emb_src, enc_Wih, enc_bih,
                                         emb_trg, dec_Wih, dec_bih);
    init_kernel<<<(NB*HH)/256, 256>>>(out, trg);

    dim3 gblk(16, 8);
    dim3 ggrid(HH/BN, NB/BM);   // (32, 8) = 256 blocks
    int p = 0;

    // encoder: token for step t is src[b*S + t] (stride S); table_sel=0
    for (int t = 0; t < SS; t++) {
        gru_step<<<ggrid, gblk>>>(p, enc_Whh, enc_bhh, 0, src + t, SS);
        p ^= 1;
    }
    // decoder: tokens from g_tok (ext_tok = nullptr); table_sel=1
    dim3 pgrid(NB/PBM, 8);
    dim3 pblk(32, 8);
    for (int t = 0; t < TT-1; t++) {
        gru_step<<<ggrid, gblk>>>(p, dec_Whh, dec_bhh, 1, (const int*)nullptr, 1);
        p ^= 1;
        pred_part<<<pgrid, pblk>>>(p, fc_W);
        argmax_write<<<NB, VV>>>(out, fc_b, trg, tfr, t + 1);
    }
}

// round 9
// speedup vs baseline: 1.1547x; 1.1547x over previous
#include <cuda_runtime.h>
#include <cuda_fp16.h>
#include <math.h>
#include <stdint.h>

#define NB 512
#define SS 128
#define TT 128
#define EE 128
#define HH 1024
#define VV 128
#define G3 (3*HH)

#define BM 128
#define BN 64
#define KS 64
#define NCHUNK (HH/KS)              // 16
#define TA_HALFS (BM*KS)            // 8192
#define TB_HALFS (BN*KS)            // 4096
#define TA_BYTES (TA_HALFS*2)       // 16384
#define TB_BYTES (TB_HALFS*2)       // 8192
#define STAGE_BYTES (3*TA_BYTES + 3*TB_BYTES)   // 73728
#define SMEM_DYN (2*STAGE_BYTES)                // 147456

#define P1 (1.0f/2048.0f)
#define P2 (1.0f/4194304.0f)
#define S1 2048.0f
#define S2 4194304.0f

// ================= device scratch =================
__device__ float g_h[2][NB*HH];                           // fp32 hidden master
__device__ __align__(16) __half g_hP[2][3][NB*HH];        // h planes, A-tile layout
__device__ __align__(16) __half g_WP[2][3][(size_t)G3*HH];// Whh planes, B-tile layout
__device__ float g_gh[(size_t)NB*G3];                     // step GEMM output
__device__ float g_Gsrc[VV*G3];
__device__ float g_Gtrg[VV*G3];
__device__ int   g_tok[NB];
__device__ float g_pred_part[8][NB*VV];

// ================= PTX helpers (portable) =================
__device__ __forceinline__ uint32_t smem_u32(const void* p) {
    uint32_t a;
    asm("{ .reg .u64 t; cvta.to.shared.u64 t, %1; cvt.u32.u64 %0, t; }" : "=r"(a) : "l"(p));
    return a;
}
#define CP16(sm, gp) \
    asm volatile("cp.async.cg.shared.global [%0], [%1], 16;" :: "r"(sm), "l"(gp) : "memory")
#define CP_COMMIT() asm volatile("cp.async.commit_group;" ::: "memory")
#define CP_WAIT1()  asm volatile("cp.async.wait_group 1;" ::: "memory")
#define CP_WAIT0()  asm volatile("cp.async.wait_group 0;" ::: "memory")
#define LDSM4(r, a) \
    asm volatile("ldmatrix.sync.aligned.m8n8.x4.shared.b16 {%0,%1,%2,%3}, [%4];" \
        : "=r"((r)[0]),"=r"((r)[1]),"=r"((r)[2]),"=r"((r)[3]) : "r"(a))
// chained MMA (in-HMMA accumulate; used only for scaled correction terms)
#define MMA16816(d, a, b0, b1) \
    asm volatile("mma.sync.aligned.m16n8k16.row.col.f32.f16.f16.f32 " \
        "{%0,%1,%2,%3}, {%4,%5,%6,%7}, {%8,%9}, {%0,%1,%2,%3};" \
        : "+f"((d)[0]),"+f"((d)[1]),"+f"((d)[2]),"+f"((d)[3]) \
        : "r"((a)[0]),"r"((a)[1]),"r"((a)[2]),"r"((a)[3]), "r"(b0),"r"(b1))
// zero-C MMA: output to fresh registers, no in-HMMA chaining (main term)
#define MMA16816_Z(d, a, b0, b1) \
    asm volatile("mma.sync.aligned.m16n8k16.row.col.f32.f16.f16.f32 " \
        "{%0,%1,%2,%3}, {%4,%5,%6,%7}, {%8,%9}, {%10,%10,%10,%10};" \
        : "=f"((d)[0]),"=f"((d)[1]),"=f"((d)[2]),"=f"((d)[3]) \
        : "r"((a)[0]),"r"((a)[1]),"r"((a)[2]),"r"((a)[3]), "r"(b0),"r"(b1), "f"(0.0f))

// swizzled half index within a tile (row pitch 128B; 16B chunk ^= row&7)
__device__ __forceinline__ int sw_half(int r, int c) {
    return r*64 + (((c>>3) ^ (r&7))<<3) + (c&7);
}
__device__ __forceinline__ uint32_t ldsm_addr(uint32_t tbase, int row, int kc) {
    return tbase + row*128 + ((((kc>>3) ^ (row&7))&7)<<4);
}
// exact 3-plane fp16 split
__device__ __forceinline__ void split3(float v, __half& h0, __half& h1, __half& h2) {
    h0 = __float2half(v);
    float r1 = v - __half2float(h0);
    h1 = __float2half(r1 * S1);
    float r2 = r1 - __half2float(h1) * P1;
    h2 = __float2half(r2 * S2);
}

// ================= build: gi tables =================
__global__ void build_tables(const float* __restrict__ emb_src,
                             const float* __restrict__ enc_Wih,
                             const float* __restrict__ enc_bih,
                             const float* __restrict__ emb_trg,
                             const float* __restrict__ dec_Wih,
                             const float* __restrict__ dec_bih)
{
    int idx = blockIdx.x * blockDim.x + threadIdx.x;
    int which = idx / (VV*G3);
    int rem   = idx % (VV*G3);
    int v = rem / G3;
    int c = rem % G3;
    const float* emb = which ? emb_trg : emb_src;
    const float* W   = which ? dec_Wih : enc_Wih;
    const float* bi  = which ? dec_bih : enc_bih;
    float s = bi[c];
    if (v != 0) {
        const float* e = emb + v*EE;
        const float* w = W + c*EE;
        #pragma unroll 8
        for (int k = 0; k < EE; k++) s += e[k]*w[k];
    }
    float* G = which ? g_Gtrg : g_Gsrc;
    G[v*G3 + c] = s;
}

// ================= build: Whh 3-plane split, B-tile layout =====================
__global__ void build_wsplit(const float* __restrict__ enc_Whh,
                             const float* __restrict__ dec_Whh)
{
    int idx = blockIdx.x * blockDim.x + threadIdx.x;   // 2*3072*1024
    int dir = idx / (G3*HH);
    int rem = idx % (G3*HH);
    int n = rem / HH;
    int k = rem % HH;
    const float* W = dir ? dec_Whh : enc_Whh;
    float v = W[n*HH + k];
    __half h0, h1, h2;
    split3(v, h0, h1, h2);
    size_t pos = (size_t)((n >> 6)*NCHUNK + (k >> 6))*TB_HALFS + sw_half(n & 63, k & 63);
    g_WP[dir][0][pos] = h0;
    g_WP[dir][1][pos] = h1;
    g_WP[dir][2][pos] = h2;
}

// ================= init =================
__global__ void init_kernel(float* __restrict__ out, const int* __restrict__ trg)
{
    int i = blockIdx.x * blockDim.x + threadIdx.x;
    if (i < NB*HH) {
        g_h[0][i] = 0.0f;
        g_hP[0][0][i] = __float2half(0.0f);
        g_hP[0][1][i] = __float2half(0.0f);
        g_hP[0][2][i] = __float2half(0.0f);
    }
    if (i < NB*VV) {
        int b = i / VV, v = i % VV;
        out[b*(TT*VV) + v] = 0.0f;
    }
    if (i < NB) g_tok[i] = trg[i*TT];
}

// ================= tensor-core GEMM: gh = h @ Whh^T, 3-plane / 6-term ==========
// Main (a0*b0) term: per-MMA zero-C + register FADD accumulate (RN) to avoid
// the in-HMMA truncation-bias chain. Corrections stay chained (scaled 2^-11/-22).
// grid (48, 4): x = n-tile (3072/64), y = m-tile (512/128). 256 threads.
__global__ __launch_bounds__(256, 1)
void gru_gemm(int pin, int dir)
{
    extern __shared__ char smc[];
    const uint32_t sbase = smem_u32(smc);
    const int tid  = threadIdx.x;
    const int wid  = tid >> 5;
    const int lane = tid & 31;
    const int nt = blockIdx.x;
    const int mt = blockIdx.y;
    const int wm = (wid >> 1) * 32;    // warp m offset: 0/32/64/96
    const int wn = (wid & 1) * 32;     // warp n offset: 0/32

    const char* gA0 = (const char*)g_hP[pin][0] + (size_t)mt*NCHUNK*TA_BYTES;
    const char* gA1 = (const char*)g_hP[pin][1] + (size_t)mt*NCHUNK*TA_BYTES;
    const char* gA2 = (const char*)g_hP[pin][2] + (size_t)mt*NCHUNK*TA_BYTES;
    const char* gB0 = (const char*)g_WP[dir][0] + (size_t)nt*NCHUNK*TB_BYTES;
    const char* gB1 = (const char*)g_WP[dir][1] + (size_t)nt*NCHUNK*TB_BYTES;
    const char* gB2 = (const char*)g_WP[dir][2] + (size_t)nt*NCHUNK*TB_BYTES;

    float acc0[2][4][4], acc1[2][4][4], acc2[2][4][4];
    #pragma unroll
    for (int i = 0; i < 2; i++)
        #pragma unroll
        for (int j = 0; j < 4; j++)
            #pragma unroll
            for (int q = 0; q < 4; q++) {
                acc0[i][j][q] = 0.0f; acc1[i][j][q] = 0.0f; acc2[i][j][q] = 0.0f;
            }

    // prologue: issue chunk 0
    {
        uint32_t sb = sbase;
        #pragma unroll
        for (int j = 0; j < 4; j++) {
            int o = (tid + 256*j) * 16;
            CP16(sb + o,               gA0 + o);
            CP16(sb + TA_BYTES + o,    gA1 + o);
            CP16(sb + 2*TA_BYTES + o,  gA2 + o);
        }
        #pragma unroll
        for (int j = 0; j < 2; j++) {
            int o = (tid + 256*j) * 16;
            CP16(sb + 3*TA_BYTES + o,              gB0 + o);
            CP16(sb + 3*TA_BYTES + TB_BYTES + o,   gB1 + o);
            CP16(sb + 3*TA_BYTES + 2*TB_BYTES + o, gB2 + o);
        }
        CP_COMMIT();
    }

    const int arow  = lane & 15;
    const int khalf = (lane >> 4) * 8;

    for (int c = 0; c < NCHUNK; c++) {
        if (c + 1 < NCHUNK) {
            uint32_t sb = sbase + ((c+1) & 1) * STAGE_BYTES;
            size_t goA = (size_t)(c+1) * TA_BYTES;
            size_t goB = (size_t)(c+1) * TB_BYTES;
            #pragma unroll
            for (int j = 0; j < 4; j++) {
                int o = (tid + 256*j) * 16;
                CP16(sb + o,               gA0 + goA + o);
                CP16(sb + TA_BYTES + o,    gA1 + goA + o);
                CP16(sb + 2*TA_BYTES + o,  gA2 + goA + o);
            }
            #pragma unroll
            for (int j = 0; j < 2; j++) {
                int o = (tid + 256*j) * 16;
                CP16(sb + 3*TA_BYTES + o,              gB0 + goB + o);
                CP16(sb + 3*TA_BYTES + TB_BYTES + o,   gB1 + goB + o);
                CP16(sb + 3*TA_BYTES + 2*TB_BYTES + o, gB2 + goB + o);
            }
            CP_COMMIT();
            CP_WAIT1();
        } else {
            CP_WAIT0();
        }
        __syncthreads();

        const uint32_t St = sbase + (c & 1) * STAGE_BYTES;
        const uint32_t A0 = St;
        const uint32_t A1 = St + TA_BYTES;
        const uint32_t A2 = St + 2*TA_BYTES;
        const uint32_t B0 = St + 3*TA_BYTES;
        const uint32_t B1 = B0 + TB_BYTES;
        const uint32_t B2 = B0 + 2*TB_BYTES;

        #pragma unroll
        for (int ks = 0; ks < 4; ks++) {
            const int kc = ks*16 + khalf;
            uint32_t a0[2][4], a1f[2][4], a2f[2][4];
            uint32_t b0[2][4], b1f[2][4], b2f[2][4];
            #pragma unroll
            for (int mi = 0; mi < 2; mi++) {
                int row = wm + mi*16 + arow;
                LDSM4(a0[mi],  ldsm_addr(A0, row, kc));
                LDSM4(a1f[mi], ldsm_addr(A1, row, kc));
                LDSM4(a2f[mi], ldsm_addr(A2, row, kc));
            }
            #pragma unroll
            for (int g = 0; g < 2; g++) {
                int row = wn + g*16 + arow;
                LDSM4(b0[g],  ldsm_addr(B0, row, kc));
                LDSM4(b1f[g], ldsm_addr(B1, row, kc));
                LDSM4(b2f[g], ldsm_addr(B2, row, kc));
            }
            #pragma unroll
            for (int mi = 0; mi < 2; mi++)
                #pragma unroll
                for (int g = 0; g < 2; g++)
                    #pragma unroll
                    for (int s = 0; s < 2; s++) {
                        const int n8 = g*2 + s;
                        // main term: zero-C MMA + RN register accumulate
                        float dt[4];
                        MMA16816_Z(dt, a0[mi], b0[g][s], b0[g][2+s]);
                        acc0[mi][n8][0] += dt[0];
                        acc0[mi][n8][1] += dt[1];
                        acc0[mi][n8][2] += dt[2];
                        acc0[mi][n8][3] += dt[3];
                        // scale 2^-11 corrections (chained; bias /2048 -> negligible)
                        MMA16816(acc1[mi][n8], a0[mi],  b1f[g][s], b1f[g][2+s]);
                        MMA16816(acc1[mi][n8], a1f[mi], b0[g][s],  b0[g][2+s]);
                        // scale 2^-22 corrections
                        MMA16816(acc2[mi][n8], a0[mi],  b2f[g][s], b2f[g][2+s]);
                        MMA16816(acc2[mi][n8], a1f[mi], b1f[g][s], b1f[g][2+s]);
                        MMA16816(acc2[mi][n8], a2f[mi], b0[g][s],  b0[g][2+s]);
                    }
        }
        __syncthreads();
    }

    // epilogue: gh = acc0 + acc1*2^-11 + acc2*2^-22
    #pragma unroll
    for (int mi = 0; mi < 2; mi++) {
        int r0 = mt*128 + wm + mi*16 + (lane >> 2);
        #pragma unroll
        for (int n8 = 0; n8 < 4; n8++) {
            int c0 = nt*64 + wn + n8*8 + (lane & 3)*2;
            float2 v0 = make_float2(
                acc0[mi][n8][0] + acc1[mi][n8][0]*P1 + acc2[mi][n8][0]*P2,
                acc0[mi][n8][1] + acc1[mi][n8][1]*P1 + acc2[mi][n8][1]*P2);
            float2 v1 = make_float2(
                acc0[mi][n8][2] + acc1[mi][n8][2]*P1 + acc2[mi][n8][2]*P2,
                acc0[mi][n8][3] + acc1[mi][n8][3]*P1 + acc2[mi][n8][3]*P2);
            *(float2*)&g_gh[(size_t)r0*G3 + c0]     = v0;
            *(float2*)&g_gh[(size_t)(r0+8)*G3 + c0] = v1;
        }
    }
}

// ================= gate epilogue: h_out + 3-plane writeback =====================
__global__ __launch_bounds__(256)
void gate_kernel(int pin, const float* __restrict__ bhh, int table_sel,
                 const int* __restrict__ ext_tok, int tok_stride)
{
    int idx = blockIdx.x * 256 + threadIdx.x;
    int row = idx >> 10;
    int col = idx & 1023;
    const int* tokp = ext_tok ? ext_tok : g_tok;
    int tok = tokp[row * tok_stride];
    const float* Grow = (table_sel ? g_Gtrg : g_Gsrc) + (size_t)tok*G3;
    const float* ghr = &g_gh[(size_t)row*G3];

    float gr = ghr[col]        + bhh[col];
    float gz = ghr[HH + col]   + bhh[HH + col];
    float gn = ghr[2*HH + col] + bhh[2*HH + col];
    float r = 1.0f / (1.0f + expf(-(Grow[col]      + gr)));
    float z = 1.0f / (1.0f + expf(-(Grow[HH + col] + gz)));
    float n = tanhf(Grow[2*HH + col] + r * gn);
    float hp = g_h[pin][row*HH + col];
    float ho = (1.0f - z)*n + z*hp;

    g_h[pin ^ 1][row*HH + col] = ho;
    __half h0, h1, h2;
    split3(ho, h0, h1, h2);
    size_t pos = (size_t)((row >> 7)*NCHUNK + (col >> 6))*TA_HALFS + sw_half(row & 127, col & 63);
    g_hP[pin ^ 1][0][pos] = h0;
    g_hP[pin ^ 1][1][pos] = h1;
    g_hP[pin ^ 1][2][pos] = h2;
}

// ================= decoder pred GEMM (split-K SIMT, fp32) =================
#define PBM 32
#define PBK 16
__global__ __launch_bounds__(256, 1)
void pred_part(int pcur, const float* __restrict__ fcW)
{
    const float* __restrict__ h = g_h[pcur];
    __shared__ float As[PBK][PBM+4];
    __shared__ float Bs[PBK][VV+4];

    const int row0 = blockIdx.x * PBM;
    const int k0   = blockIdx.y * (HH/8);
    const int tx = threadIdx.x, ty = threadIdx.y;
    const int tid = ty*32 + tx;

    float acc[4][4];
    #pragma unroll
    for (int i = 0; i < 4; i++)
        #pragma unroll
        for (int j = 0; j < 4; j++) acc[i][j] = 0.0f;

    for (int kt = 0; kt < HH/8; kt += PBK) {
        if (tid < 128) {
            int ar = tid >> 2;
            int ak = (tid & 3) << 2;
            float4 av = *(const float4*)&h[(row0+ar)*HH + k0 + kt + ak];
            As[ak+0][ar] = av.x; As[ak+1][ar] = av.y;
            As[ak+2][ar] = av.z; As[ak+3][ar] = av.w;
        }
        #pragma unroll
        for (int l = 0; l < 2; l++) {
            int t2 = l*256 + tid;
            int bc = t2 >> 2;
            int bk = (t2 & 3) << 2;
            float4 bv = *(const float4*)&fcW[bc*HH + k0 + kt + bk];
            Bs[bk+0][bc] = bv.x; Bs[bk+1][bc] = bv.y;
            Bs[bk+2][bc] = bv.z; Bs[bk+3][bc] = bv.w;
        }
        __syncthreads();
        #pragma unroll
        for (int kk = 0; kk < PBK; kk++) {
            float4 a = *(const float4*)&As[kk][ty*4];
            float4 b = *(const float4*)&Bs[kk][tx*4];
            float av[4] = {a.x,a.y,a.z,a.w};
            float bv[4] = {b.x,b.y,b.z,b.w};
            #pragma unroll
            for (int i = 0; i < 4; i++)
                #pragma unroll
                for (int j = 0; j < 4; j++) acc[i][j] += av[i]*bv[j];
        }
        __syncthreads();
    }
    float* dst = g_pred_part[blockIdx.y];
    #pragma unroll
    for (int i = 0; i < 4; i++)
        #pragma unroll
        for (int j = 0; j < 4; j++)
            dst[(row0 + ty*4 + i)*VV + tx*4 + j] = acc[i][j];
}

// ================= reduce + bias + out + argmax -> next token =================
__global__ void argmax_write(float* __restrict__ out,
                             const float* __restrict__ fcb,
                             const int* __restrict__ trg,
                             const void* __restrict__ tfr,
                             int t_out)
{
    int b = blockIdx.x;
    int v = threadIdx.x;
    float acc = fcb[v];
    #pragma unroll
    for (int p = 0; p < 8; p++) acc += g_pred_part[p][b*VV + v];
    out[b*(TT*VV) + t_out*VV + v] = acc;

    __shared__ float sval[128];
    __shared__ int   sidx[128];
    sval[v] = acc; sidx[v] = v;
    __syncthreads();
    for (int s = 64; s > 0; s >>= 1) {
        if (v < s) {
            if (sval[v+s] > sval[v] ||
                (sval[v+s] == sval[v] && sidx[v+s] < sidx[v])) {
                sval[v] = sval[v+s]; sidx[v] = sidx[v+s];
            }
        }
        __syncthreads();
    }
    if (v == 0) {
        int   ti  = ((const int*)tfr)[0];
        float tfv = ((const float*)tfr)[0];
        bool tf = (ti > 0) || (tfv > 0.0f);
        g_tok[b] = tf ? trg[b*TT + t_out] : sidx[0];
    }
}

// ================= host =================
extern "C" void kernel_launch(void* const* d_in, const int* in_sizes, int n_in,
                              void* d_out, int out_size)
{
    const int*   src     = (const int*)  d_in[0];
    const int*   trg     = (const int*)  d_in[1];
    const float* emb_src = (const float*)d_in[2];
    const float* emb_trg = (const float*)d_in[3];
    const float* enc_Wih = (const float*)d_in[4];
    const float* enc_Whh = (const float*)d_in[5];
    const float* enc_bih = (const float*)d_in[6];
    const float* enc_bhh = (const float*)d_in[7];
    const float* dec_Wih = (const float*)d_in[8];
    const float* dec_Whh = (const float*)d_in[9];
    const float* dec_bih = (const float*)d_in[10];
    const float* dec_bhh = (const float*)d_in[11];
    const float* fc_W    = (const float*)d_in[12];
    const float* fc_b    = (const float*)d_in[13];
    const void*  tfr     =               d_in[14];
    float* out = (float*)d_out;

    cudaFuncSetAttribute(gru_gemm, cudaFuncAttributeMaxDynamicSharedMemorySize, SMEM_DYN);

    build_tables<<<(2*VV*G3)/256, 256>>>(emb_src, enc_Wih, enc_bih,
                                         emb_trg, dec_Wih, dec_bih);
    build_wsplit<<<(2*G3*HH)/256, 256>>>(enc_Whh, dec_Whh);
    init_kernel<<<(NB*HH)/256, 256>>>(out, trg);

    dim3 ggrid(G3/BN, NB/BM);   // (48, 4)
    int p = 0;

    // encoder
    for (int t = 0; t < SS; t++) {
        gru_gemm<<<ggrid, 256, SMEM_DYN>>>(p, 0);
        gate_kernel<<<(NB*HH)/256, 256>>>(p, enc_bhh, 0, src + t, SS);
        p ^= 1;
    }
    // decoder
    dim3 pgrid(NB/PBM, 8);
    dim3 pblk(32, 8);
    for (int t = 0; t < TT-1; t++) {
        gru_gemm<<<ggrid, 256, SMEM_DYN>>>(p, 1);
        gate_kernel<<<(NB*HH)/256, 256>>>(p, dec_bhh, 1, (const int*)nullptr, 1);
        p ^= 1;
        pred_part<<<pgrid, pblk>>>(p, fc_W);
        argmax_write<<<NB, VV>>>(out, fc_b, trg, tfr, t + 1);
    }
}

// round 10
// speedup vs baseline: 1.9783x; 1.7132x over previous
#include <cuda_runtime.h>
#include <cuda_fp16.h>
#include <math.h>
#include <stdint.h>

#define NB 512
#define SS 128
#define TT 128
#define EE 128
#define HH 1024
#define VV 128
#define G3 (3*HH)

#define BM 128
#define BN 64
#define KS 64
#define NCHUNK (HH/KS)              // 16
#define TA_HALFS (BM*KS)            // 8192
#define TB_HALFS (BN*KS)            // 4096
#define TA_BYTES (TA_HALFS*2)       // 16384
#define TB_BYTES (TB_HALFS*2)       // 8192
#define STAGE_BYTES (2*TA_BYTES + 2*TB_BYTES)   // 49152
#define SMEM_DYN (2*STAGE_BYTES)                // 98304

#define P1 (1.0f/2048.0f)
#define S1 2048.0f

// ================= device scratch =================
__device__ float g_h[2][NB*HH];                           // fp32 hidden master
__device__ __align__(16) __half g_hP[2][2][NB*HH];        // h planes, A-tile layout
__device__ __align__(16) __half g_WP[2][2][(size_t)G3*HH];// Whh planes, B-tile layout
__device__ float g_gh[(size_t)NB*G3];                     // step GEMM output
__device__ float g_Gsrc[VV*G3];
__device__ float g_Gtrg[VV*G3];
__device__ int   g_tok[NB];
__device__ float g_pred_part[8][NB*VV];

// ================= PTX helpers (portable) =================
__device__ __forceinline__ uint32_t smem_u32(const void* p) {
    uint32_t a;
    asm("{ .reg .u64 t; cvta.to.shared.u64 t, %1; cvt.u32.u64 %0, t; }" : "=r"(a) : "l"(p));
    return a;
}
#define CP16(sm, gp) \
    asm volatile("cp.async.cg.shared.global [%0], [%1], 16;" :: "r"(sm), "l"(gp) : "memory")
#define CP_COMMIT() asm volatile("cp.async.commit_group;" ::: "memory")
#define CP_WAIT1()  asm volatile("cp.async.wait_group 1;" ::: "memory")
#define CP_WAIT0()  asm volatile("cp.async.wait_group 0;" ::: "memory")
#define LDSM4(r, a) \
    asm volatile("ldmatrix.sync.aligned.m8n8.x4.shared.b16 {%0,%1,%2,%3}, [%4];" \
        : "=r"((r)[0]),"=r"((r)[1]),"=r"((r)[2]),"=r"((r)[3]) : "r"(a))
// chained MMA (in-HMMA accumulate; used only for the 2^-11-scaled cross terms)
#define MMA16816(d, a, b0, b1) \
    asm volatile("mma.sync.aligned.m16n8k16.row.col.f32.f16.f16.f32 " \
        "{%0,%1,%2,%3}, {%4,%5,%6,%7}, {%8,%9}, {%0,%1,%2,%3};" \
        : "+f"((d)[0]),"+f"((d)[1]),"+f"((d)[2]),"+f"((d)[3]) \
        : "r"((a)[0]),"r"((a)[1]),"r"((a)[2]),"r"((a)[3]), "r"(b0),"r"(b1))
// zero-C MMA: output to fresh registers, no in-HMMA chaining (main term)
#define MMA16816_Z(d, a, b0, b1) \
    asm volatile("mma.sync.aligned.m16n8k16.row.col.f32.f16.f16.f32 " \
        "{%0,%1,%2,%3}, {%4,%5,%6,%7}, {%8,%9}, {%10,%10,%10,%10};" \
        : "=f"((d)[0]),"=f"((d)[1]),"=f"((d)[2]),"=f"((d)[3]) \
        : "r"((a)[0]),"r"((a)[1]),"r"((a)[2]),"r"((a)[3]), "r"(b0),"r"(b1), "f"(0.0f))

// swizzled half index within a tile (row pitch 128B; 16B chunk ^= row&7)
__device__ __forceinline__ int sw_half(int r, int c) {
    return r*64 + (((c>>3) ^ (r&7))<<3) + (c&7);
}
__device__ __forceinline__ uint32_t ldsm_addr(uint32_t tbase, int row, int kc) {
    return tbase + row*128 + ((((kc>>3) ^ (row&7))&7)<<4);
}
// exact 2-plane fp16 split (lo scaled by 2048 into normal range)
__device__ __forceinline__ void split2(float v, __half& h0, __half& h1) {
    h0 = __float2half(v);
    float r1 = v - __half2float(h0);
    h1 = __float2half(r1 * S1);
}

// ================= build: gi tables =================
__global__ void build_tables(const float* __restrict__ emb_src,
                             const float* __restrict__ enc_Wih,
                             const float* __restrict__ enc_bih,
                             const float* __restrict__ emb_trg,
                             const float* __restrict__ dec_Wih,
                             const float* __restrict__ dec_bih)
{
    int idx = blockIdx.x * blockDim.x + threadIdx.x;
    int which = idx / (VV*G3);
    int rem   = idx % (VV*G3);
    int v = rem / G3;
    int c = rem % G3;
    const float* emb = which ? emb_trg : emb_src;
    const float* W   = which ? dec_Wih : enc_Wih;
    const float* bi  = which ? dec_bih : enc_bih;
    float s = bi[c];
    if (v != 0) {
        const float* e = emb + v*EE;
        const float* w = W + c*EE;
        #pragma unroll 8
        for (int k = 0; k < EE; k++) s += e[k]*w[k];
    }
    float* G = which ? g_Gtrg : g_Gsrc;
    G[v*G3 + c] = s;
}

// ================= build: Whh 2-plane split, B-tile layout =====================
__global__ void build_wsplit(const float* __restrict__ enc_Whh,
                             const float* __restrict__ dec_Whh)
{
    int idx = blockIdx.x * blockDim.x + threadIdx.x;   // 2*3072*1024
    int dir = idx / (G3*HH);
    int rem = idx % (G3*HH);
    int n = rem / HH;
    int k = rem % HH;
    const float* W = dir ? dec_Whh : enc_Whh;
    float v = W[n*HH + k];
    __half h0, h1;
    split2(v, h0, h1);
    size_t pos = (size_t)((n >> 6)*NCHUNK + (k >> 6))*TB_HALFS + sw_half(n & 63, k & 63);
    g_WP[dir][0][pos] = h0;
    g_WP[dir][1][pos] = h1;
}

// ================= init =================
__global__ void init_kernel(float* __restrict__ out, const int* __restrict__ trg)
{
    int i = blockIdx.x * blockDim.x + threadIdx.x;
    if (i < NB*HH) {
        g_h[0][i] = 0.0f;
        g_hP[0][0][i] = __float2half(0.0f);
        g_hP[0][1][i] = __float2half(0.0f);
    }
    if (i < NB*VV) {
        int b = i / VV, v = i % VV;
        out[b*(TT*VV) + v] = 0.0f;
    }
    if (i < NB) g_tok[i] = trg[i*TT];
}

// ================= tensor-core GEMM: gh = h @ Whh^T, 2-plane / 3-term ==========
// Main (a0*b0): zero-C MMA + RN register FADD (kills RZ-chain bias).
// Cross terms (a0*b1', a1'*b0): chained in-HMMA into acc1 (bias enters *2^-11).
// a1*b1 term dropped (2^-22-scale, below fp32 noise).
// grid (48, 4). 256 threads. 2 CTAs/SM (48KB stage x2 buffers = 96KB dyn smem).
__global__ __launch_bounds__(256, 2)
void gru_gemm(int pin, int dir)
{
    extern __shared__ char smc[];
    const uint32_t sbase = smem_u32(smc);
    const int tid  = threadIdx.x;
    const int wid  = tid >> 5;
    const int lane = tid & 31;
    const int nt = blockIdx.x;
    const int mt = blockIdx.y;
    const int wm = (wid >> 1) * 32;    // warp m offset: 0/32/64/96
    const int wn = (wid & 1) * 32;     // warp n offset: 0/32

    const char* gA0 = (const char*)g_hP[pin][0] + (size_t)mt*NCHUNK*TA_BYTES;
    const char* gA1 = (const char*)g_hP[pin][1] + (size_t)mt*NCHUNK*TA_BYTES;
    const char* gB0 = (const char*)g_WP[dir][0] + (size_t)nt*NCHUNK*TB_BYTES;
    const char* gB1 = (const char*)g_WP[dir][1] + (size_t)nt*NCHUNK*TB_BYTES;

    float acc0[2][4][4], acc1[2][4][4];
    #pragma unroll
    for (int i = 0; i < 2; i++)
        #pragma unroll
        for (int j = 0; j < 4; j++)
            #pragma unroll
            for (int q = 0; q < 4; q++) { acc0[i][j][q] = 0.0f; acc1[i][j][q] = 0.0f; }

    // prologue: issue chunk 0
    {
        uint32_t sb = sbase;
        #pragma unroll
        for (int j = 0; j < 4; j++) {
            int o = (tid + 256*j) * 16;
            CP16(sb + o,            gA0 + o);
            CP16(sb + TA_BYTES + o, gA1 + o);
        }
        #pragma unroll
        for (int j = 0; j < 2; j++) {
            int o = (tid + 256*j) * 16;
            CP16(sb + 2*TA_BYTES + o,            gB0 + o);
            CP16(sb + 2*TA_BYTES + TB_BYTES + o, gB1 + o);
        }
        CP_COMMIT();
    }

    const int arow  = lane & 15;
    const int khalf = (lane >> 4) * 8;

    for (int c = 0; c < NCHUNK; c++) {
        if (c + 1 < NCHUNK) {
            uint32_t sb = sbase + ((c+1) & 1) * STAGE_BYTES;
            size_t goA = (size_t)(c+1) * TA_BYTES;
            size_t goB = (size_t)(c+1) * TB_BYTES;
            #pragma unroll
            for (int j = 0; j < 4; j++) {
                int o = (tid + 256*j) * 16;
                CP16(sb + o,            gA0 + goA + o);
                CP16(sb + TA_BYTES + o, gA1 + goA + o);
            }
            #pragma unroll
            for (int j = 0; j < 2; j++) {
                int o = (tid + 256*j) * 16;
                CP16(sb + 2*TA_BYTES + o,            gB0 + goB + o);
                CP16(sb + 2*TA_BYTES + TB_BYTES + o, gB1 + goB + o);
            }
            CP_COMMIT();
            CP_WAIT1();
        } else {
            CP_WAIT0();
        }
        __syncthreads();

        const uint32_t St = sbase + (c & 1) * STAGE_BYTES;
        const uint32_t A0 = St;
        const uint32_t A1 = St + TA_BYTES;
        const uint32_t B0 = St + 2*TA_BYTES;
        const uint32_t B1 = B0 + TB_BYTES;

        #pragma unroll
        for (int ks = 0; ks < 4; ks++) {
            const int kc = ks*16 + khalf;
            uint32_t a0[2][4], a1f[2][4];
            uint32_t b0[2][4], b1f[2][4];
            #pragma unroll
            for (int mi = 0; mi < 2; mi++) {
                int row = wm + mi*16 + arow;
                LDSM4(a0[mi],  ldsm_addr(A0, row, kc));
                LDSM4(a1f[mi], ldsm_addr(A1, row, kc));
            }
            #pragma unroll
            for (int g = 0; g < 2; g++) {
                int row = wn + g*16 + arow;
                LDSM4(b0[g],  ldsm_addr(B0, row, kc));
                LDSM4(b1f[g], ldsm_addr(B1, row, kc));
            }
            #pragma unroll
            for (int mi = 0; mi < 2; mi++)
                #pragma unroll
                for (int g = 0; g < 2; g++)
                    #pragma unroll
                    for (int s = 0; s < 2; s++) {
                        const int n8 = g*2 + s;
                        // main term: zero-C MMA + RN register accumulate
                        float dt[4];
                        MMA16816_Z(dt, a0[mi], b0[g][s], b0[g][2+s]);
                        acc0[mi][n8][0] += dt[0];
                        acc0[mi][n8][1] += dt[1];
                        acc0[mi][n8][2] += dt[2];
                        acc0[mi][n8][3] += dt[3];
                        // 2^-11-scaled cross terms (chained; bias negligible)
                        MMA16816(acc1[mi][n8], a0[mi],  b1f[g][s], b1f[g][2+s]);
                        MMA16816(acc1[mi][n8], a1f[mi], b0[g][s],  b0[g][2+s]);
                    }
        }
        __syncthreads();
    }

    // epilogue: gh = acc0 + acc1*2^-11
    #pragma unroll
    for (int mi = 0; mi < 2; mi++) {
        int r0 = mt*128 + wm + mi*16 + (lane >> 2);
        #pragma unroll
        for (int n8 = 0; n8 < 4; n8++) {
            int c0 = nt*64 + wn + n8*8 + (lane & 3)*2;
            float2 v0 = make_float2(acc0[mi][n8][0] + acc1[mi][n8][0]*P1,
                                    acc0[mi][n8][1] + acc1[mi][n8][1]*P1);
            float2 v1 = make_float2(acc0[mi][n8][2] + acc1[mi][n8][2]*P1,
                                    acc0[mi][n8][3] + acc1[mi][n8][3]*P1);
            *(float2*)&g_gh[(size_t)r0*G3 + c0]     = v0;
            *(float2*)&g_gh[(size_t)(r0+8)*G3 + c0] = v1;
        }
    }
}

// ================= gate epilogue: h_out + 2-plane writeback =====================
__global__ __launch_bounds__(256)
void gate_kernel(int pin, const float* __restrict__ bhh, int table_sel,
                 const int* __restrict__ ext_tok, int tok_stride)
{
    int idx = blockIdx.x * 256 + threadIdx.x;
    int row = idx >> 10;
    int col = idx & 1023;
    const int* tokp = ext_tok ? ext_tok : g_tok;
    int tok = tokp[row * tok_stride];
    const float* Grow = (table_sel ? g_Gtrg : g_Gsrc) + (size_t)tok*G3;
    const float* ghr = &g_gh[(size_t)row*G3];

    float gr = ghr[col]        + bhh[col];
    float gz = ghr[HH + col]   + bhh[HH + col];
    float gn = ghr[2*HH + col] + bhh[2*HH + col];
    float r = 1.0f / (1.0f + expf(-(Grow[col]      + gr)));
    float z = 1.0f / (1.0f + expf(-(Grow[HH + col] + gz)));
    float n = tanhf(Grow[2*HH + col] + r * gn);
    float hp = g_h[pin][row*HH + col];
    float ho = (1.0f - z)*n + z*hp;

    g_h[pin ^ 1][row*HH + col] = ho;
    __half h0, h1;
    split2(ho, h0, h1);
    size_t pos = (size_t)((row >> 7)*NCHUNK + (col >> 6))*TA_HALFS + sw_half(row & 127, col & 63);
    g_hP[pin ^ 1][0][pos] = h0;
    g_hP[pin ^ 1][1][pos] = h1;
}

// ================= decoder pred GEMM (split-K SIMT, fp32) =================
#define PBM 32
#define PBK 16
__global__ __launch_bounds__(256, 1)
void pred_part(int pcur, const float* __restrict__ fcW)
{
    const float* __restrict__ h = g_h[pcur];
    __shared__ float As[PBK][PBM+4];
    __shared__ float Bs[PBK][VV+4];

    const int row0 = blockIdx.x * PBM;
    const int k0   = blockIdx.y * (HH/8);
    const int tx = threadIdx.x, ty = threadIdx.y;
    const int tid = ty*32 + tx;

    float acc[4][4];
    #pragma unroll
    for (int i = 0; i < 4; i++)
        #pragma unroll
        for (int j = 0; j < 4; j++) acc[i][j] = 0.0f;

    for (int kt = 0; kt < HH/8; kt += PBK) {
        if (tid < 128) {
            int ar = tid >> 2;
            int ak = (tid & 3) << 2;
            float4 av = *(const float4*)&h[(row0+ar)*HH + k0 + kt + ak];
            As[ak+0][ar] = av.x; As[ak+1][ar] = av.y;
            As[ak+2][ar] = av.z; As[ak+3][ar] = av.w;
        }
        #pragma unroll
        for (int l = 0; l < 2; l++) {
            int t2 = l*256 + tid;
            int bc = t2 >> 2;
            int bk = (t2 & 3) << 2;
            float4 bv = *(const float4*)&fcW[bc*HH + k0 + kt + bk];
            Bs[bk+0][bc] = bv.x; Bs[bk+1][bc] = bv.y;
            Bs[bk+2][bc] = bv.z; Bs[bk+3][bc] = bv.w;
        }
        __syncthreads();
        #pragma unroll
        for (int kk = 0; kk < PBK; kk++) {
            float4 a = *(const float4*)&As[kk][ty*4];
            float4 b = *(const float4*)&Bs[kk][tx*4];
            float av[4] = {a.x,a.y,a.z,a.w};
            float bv[4] = {b.x,b.y,b.z,b.w};
            #pragma unroll
            for (int i = 0; i < 4; i++)
                #pragma unroll
                for (int j = 0; j < 4; j++) acc[i][j] += av[i]*bv[j];
        }
        __syncthreads();
    }
    float* dst = g_pred_part[blockIdx.y];
    #pragma unroll
    for (int i = 0; i < 4; i++)
        #pragma unroll
        for (int j = 0; j < 4; j++)
            dst[(row0 + ty*4 + i)*VV + tx*4 + j] = acc[i][j];
}

// ================= reduce + bias + out + argmax -> next token =================
__global__ void argmax_write(float* __restrict__ out,
                             const float* __restrict__ fcb,
                             const int* __restrict__ trg,
                             const void* __restrict__ tfr,
                             int t_out)
{
    int b = blockIdx.x;
    int v = threadIdx.x;
    float acc = fcb[v];
    #pragma unroll
    for (int p = 0; p < 8; p++) acc += g_pred_part[p][b*VV + v];
    out[b*(TT*VV) + t_out*VV + v] = acc;

    __shared__ float sval[128];
    __shared__ int   sidx[128];
    sval[v] = acc; sidx[v] = v;
    __syncthreads();
    for (int s = 64; s > 0; s >>= 1) {
        if (v < s) {
            if (sval[v+s] > sval[v] ||
                (sval[v+s] == sval[v] && sidx[v+s] < sidx[v])) {
                sval[v] = sval[v+s]; sidx[v] = sidx[v+s];
            }
        }
        __syncthreads();
    }
    if (v == 0) {
        int   ti  = ((const int*)tfr)[0];
        float tfv = ((const float*)tfr)[0];
        bool tf = (ti > 0) || (tfv > 0.0f);
        g_tok[b] = tf ? trg[b*TT + t_out] : sidx[0];
    }
}

// ================= host =================
extern "C" void kernel_launch(void* const* d_in, const int* in_sizes, int n_in,
                              void* d_out, int out_size)
{
    const int*   src     = (const int*)  d_in[0];
    const int*   trg     = (const int*)  d_in[1];
    const float* emb_src = (const float*)d_in[2];
    const float* emb_trg = (const float*)d_in[3];
    const float* enc_Wih = (const float*)d_in[4];
    const float* enc_Whh = (const float*)d_in[5];
    const float* enc_bih = (const float*)d_in[6];
    const float* enc_bhh = (const float*)d_in[7];
    const float* dec_Wih = (const float*)d_in[8];
    const float* dec_Whh = (const float*)d_in[9];
    const float* dec_bih = (const float*)d_in[10];
    const float* dec_bhh = (const float*)d_in[11];
    const float* fc_W    = (const float*)d_in[12];
    const float* fc_b    = (const float*)d_in[13];
    const void*  tfr     =               d_in[14];
    float* out = (float*)d_out;

    cudaFuncSetAttribute(gru_gemm, cudaFuncAttributeMaxDynamicSharedMemorySize, SMEM_DYN);

    build_tables<<<(2*VV*G3)/256, 256>>>(emb_src, enc_Wih, enc_bih,
                                         emb_trg, dec_Wih, dec_bih);
    build_wsplit<<<(2*G3*HH)/256, 256>>>(enc_Whh, dec_Whh);
    init_kernel<<<(NB*HH)/256, 256>>>(out, trg);

    dim3 ggrid(G3/BN, NB/BM);   // (48, 4)
    int p = 0;

    // encoder
    for (int t = 0; t < SS; t++) {
        gru_gemm<<<ggrid, 256, SMEM_DYN>>>(p, 0);
        gate_kernel<<<(NB*HH)/256, 256>>>(p, enc_bhh, 0, src + t, SS);
        p ^= 1;
    }
    // decoder
    dim3 pgrid(NB/PBM, 8);
    dim3 pblk(32, 8);
    for (int t = 0; t < TT-1; t++) {
        gru_gemm<<<ggrid, 256, SMEM_DYN>>>(p, 1);
        gate_kernel<<<(NB*HH)/256, 256>>>(p, dec_bhh, 1, (const int*)nullptr, 1);
        p ^= 1;
        pred_part<<<pgrid, pblk>>>(p, fc_W);
        argmax_write<<<NB, VV>>>(out, fc_b, trg, tfr, t + 1);
    }
}

// round 11
// speedup vs baseline: 2.3232x; 1.1744x over previous
#include <cuda_runtime.h>
#include <cuda_fp16.h>
#include <math.h>
#include <stdint.h>

#define NB 512
#define SS 128
#define TT 128
#define EE 128
#define HH 1024
#define VV 128
#define G3 (3*HH)

#define BM 64                      // batch rows per block
#define HCOL 32                    // h-columns per block
#define BNR 96                     // B rows per block (3 gates x 32)
#define KS 64
#define NCHUNK (HH/KS)             // 16
#define TA_HALFS (BM*KS)           // 4096
#define TB_HALFS (BNR*KS)          // 6144
#define TA_BYTES (TA_HALFS*2)      // 8192
#define TB_BYTES (TB_HALFS*2)      // 12288
#define STAGE_BYTES (2*TA_BYTES + 2*TB_BYTES)   // 40960
#define SMEM_DYN (2*STAGE_BYTES)                // 81920
#define GHS_PITCH 100              // fp32 pitch for epilogue exchange

#define P1 (1.0f/2048.0f)
#define S1 2048.0f

// ================= device scratch =================
__device__ float g_h[2][NB*HH];                           // fp32 hidden master
__device__ __align__(16) __half g_hP[2][2][NB*HH];        // h planes, 64x64 A-tile layout
__device__ __align__(16) __half g_WP[2][2][(size_t)G3*HH];// Whh planes, gate-interleaved B-tiles
__device__ float g_Gsrc[VV*G3];
__device__ float g_Gtrg[VV*G3];
__device__ int   g_tok[NB];
__device__ float g_pred_part[8][NB*VV];

// ================= PTX helpers (portable) =================
__device__ __forceinline__ uint32_t smem_u32(const void* p) {
    uint32_t a;
    asm("{ .reg .u64 t; cvta.to.shared.u64 t, %1; cvt.u32.u64 %0, t; }" : "=r"(a) : "l"(p));
    return a;
}
#define CP16(sm, gp) \
    asm volatile("cp.async.cg.shared.global [%0], [%1], 16;" :: "r"(sm), "l"(gp) : "memory")
#define CP_COMMIT() asm volatile("cp.async.commit_group;" ::: "memory")
#define CP_WAIT1()  asm volatile("cp.async.wait_group 1;" ::: "memory")
#define CP_WAIT0()  asm volatile("cp.async.wait_group 0;" ::: "memory")
#define LDSM4(r, a) \
    asm volatile("ldmatrix.sync.aligned.m8n8.x4.shared.b16 {%0,%1,%2,%3}, [%4];" \
        : "=r"((r)[0]),"=r"((r)[1]),"=r"((r)[2]),"=r"((r)[3]) : "r"(a))
// chained MMA (in-HMMA accumulate; only for the 2^-11-scaled cross terms)
#define MMA16816(d, a, b0, b1) \
    asm volatile("mma.sync.aligned.m16n8k16.row.col.f32.f16.f16.f32 " \
        "{%0,%1,%2,%3}, {%4,%5,%6,%7}, {%8,%9}, {%0,%1,%2,%3};" \
        : "+f"((d)[0]),"+f"((d)[1]),"+f"((d)[2]),"+f"((d)[3]) \
        : "r"((a)[0]),"r"((a)[1]),"r"((a)[2]),"r"((a)[3]), "r"(b0),"r"(b1))
// zero-C MMA: fresh outputs, no in-HMMA chaining (main term, RN reg accumulate)
#define MMA16816_Z(d, a, b0, b1) \
    asm volatile("mma.sync.aligned.m16n8k16.row.col.f32.f16.f16.f32 " \
        "{%0,%1,%2,%3}, {%4,%5,%6,%7}, {%8,%9}, {%10,%10,%10,%10};" \
        : "=f"((d)[0]),"=f"((d)[1]),"=f"((d)[2]),"=f"((d)[3]) \
        : "r"((a)[0]),"r"((a)[1]),"r"((a)[2]),"r"((a)[3]), "r"(b0),"r"(b1), "f"(0.0f))

// swizzled half index within a tile (row pitch 128B; 16B chunk ^= row&7)
__device__ __forceinline__ int sw_half(int r, int c) {
    return r*64 + (((c>>3) ^ (r&7))<<3) + (c&7);
}
__device__ __forceinline__ uint32_t ldsm_addr(uint32_t tbase, int row, int kc) {
    return tbase + row*128 + ((((kc>>3) ^ (row&7))&7)<<4);
}
// exact 2-plane fp16 split (lo scaled by 2048 into normal range)
__device__ __forceinline__ void split2(float v, __half& h0, __half& h1) {
    h0 = __float2half(v);
    float r1 = v - __half2float(h0);
    h1 = __float2half(r1 * S1);
}

// ================= build: gi tables =================
__global__ void build_tables(const float* __restrict__ emb_src,
                             const float* __restrict__ enc_Wih,
                             const float* __restrict__ enc_bih,
                             const float* __restrict__ emb_trg,
                             const float* __restrict__ dec_Wih,
                             const float* __restrict__ dec_bih)
{
    int idx = blockIdx.x * blockDim.x + threadIdx.x;
    int which = idx / (VV*G3);
    int rem   = idx % (VV*G3);
    int v = rem / G3;
    int c = rem % G3;
    const float* emb = which ? emb_trg : emb_src;
    const float* W   = which ? dec_Wih : enc_Wih;
    const float* bi  = which ? dec_bih : enc_bih;
    float s = bi[c];
    if (v != 0) {
        const float* e = emb + v*EE;
        const float* w = W + c*EE;
        #pragma unroll 8
        for (int k = 0; k < EE; k++) s += e[k]*w[k];
    }
    float* G = which ? g_Gtrg : g_Gsrc;
    G[v*G3 + c] = s;
}

// ===== build: Whh 2-plane split, gate-interleaved B-tile layout =====
// B tile for (nt, kc): 96 rows = gate*32 + (h&31) for h in [nt*32, nt*32+32)
__global__ void build_wsplit(const float* __restrict__ enc_Whh,
                             const float* __restrict__ dec_Whh)
{
    int idx = blockIdx.x * blockDim.x + threadIdx.x;   // 2*3072*1024
    int dir = idx / (G3*HH);
    int rem = idx % (G3*HH);
    int n = rem / HH;          // Whh row: gate*1024 + h
    int k = rem % HH;
    const float* W = dir ? dec_Whh : enc_Whh;
    float v = W[n*HH + k];
    __half h0, h1;
    split2(v, h0, h1);
    int gate = n >> 10;
    int h    = n & 1023;
    int nt   = h >> 5;
    int trow = gate*32 + (h & 31);
    size_t pos = ((size_t)nt*NCHUNK + (k >> 6))*TB_HALFS + sw_half(trow, k & 63);
    g_WP[dir][0][pos] = h0;
    g_WP[dir][1][pos] = h1;
}

// ================= init =================
__global__ void init_kernel(float* __restrict__ out, const int* __restrict__ trg)
{
    int i = blockIdx.x * blockDim.x + threadIdx.x;
    if (i < NB*HH) {
        g_h[0][i] = 0.0f;
        g_hP[0][0][i] = __float2half(0.0f);
        g_hP[0][1][i] = __float2half(0.0f);
    }
    if (i < NB*VV) {
        int b = i / VV, v = i % VV;
        out[b*(TT*VV) + v] = 0.0f;
    }
    if (i < NB) g_tok[i] = trg[i*TT];
}

// ====== fused GRU step: gate-triple tensor GEMM + gate epilogue ======
// grid (32, 8): x = h-col tile (1024/32), y = m-tile (512/64). 256 threads, 2 CTAs/SM.
// Per block: gh for 64 rows x (3 gates x 32 h-cols), then gate math + h/plane writeback.
__global__ __launch_bounds__(256, 2)
void gru_gemm(int pin, int dir, int table_sel,
              const int* __restrict__ ext_tok, int tok_stride,
              const float* __restrict__ bhh)
{
    extern __shared__ char smc[];
    const uint32_t sbase = smem_u32(smc);
    const int tid  = threadIdx.x;
    const int wid  = tid >> 5;
    const int lane = tid & 31;
    const int nt = blockIdx.x;           // h-col tile
    const int mt = blockIdx.y;           // m tile
    const int wm = (wid >> 1) * 16;      // warp m offset: 0/16/32/48
    const int wn = (wid & 1) * 48;       // warp B-row offset: 0/48

    const char* gA0 = (const char*)g_hP[pin][0] + (size_t)mt*NCHUNK*TA_BYTES;
    const char* gA1 = (const char*)g_hP[pin][1] + (size_t)mt*NCHUNK*TA_BYTES;
    const char* gB0 = (const char*)g_WP[dir][0] + (size_t)nt*NCHUNK*TB_BYTES;
    const char* gB1 = (const char*)g_WP[dir][1] + (size_t)nt*NCHUNK*TB_BYTES;

    float acc0[6][4], acc1[6][4];
    #pragma unroll
    for (int j = 0; j < 6; j++)
        #pragma unroll
        for (int q = 0; q < 4; q++) { acc0[j][q] = 0.0f; acc1[j][q] = 0.0f; }

    // prologue: issue chunk 0
    {
        uint32_t sb = sbase;
        #pragma unroll
        for (int j = 0; j < 2; j++) {
            int o = (tid + 256*j) * 16;
            CP16(sb + o,            gA0 + o);
            CP16(sb + TA_BYTES + o, gA1 + o);
        }
        #pragma unroll
        for (int j = 0; j < 3; j++) {
            int o = (tid + 256*j) * 16;
            CP16(sb + 2*TA_BYTES + o,            gB0 + o);
            CP16(sb + 2*TA_BYTES + TB_BYTES + o, gB1 + o);
        }
        CP_COMMIT();
    }

    const int arow  = lane & 15;
    const int khalf = (lane >> 4) * 8;

    for (int c = 0; c < NCHUNK; c++) {
        if (c + 1 < NCHUNK) {
            uint32_t sb = sbase + ((c+1) & 1) * STAGE_BYTES;
            size_t goA = (size_t)(c+1) * TA_BYTES;
            size_t goB = (size_t)(c+1) * TB_BYTES;
            #pragma unroll
            for (int j = 0; j < 2; j++) {
                int o = (tid + 256*j) * 16;
                CP16(sb + o,            gA0 + goA + o);
                CP16(sb + TA_BYTES + o, gA1 + goA + o);
            }
            #pragma unroll
            for (int j = 0; j < 3; j++) {
                int o = (tid + 256*j) * 16;
                CP16(sb + 2*TA_BYTES + o,            gB0 + goB + o);
                CP16(sb + 2*TA_BYTES + TB_BYTES + o, gB1 + goB + o);
            }
            CP_COMMIT();
            CP_WAIT1();
        } else {
            CP_WAIT0();
        }
        __syncthreads();

        const uint32_t St = sbase + (c & 1) * STAGE_BYTES;
        const uint32_t A0 = St;
        const uint32_t A1 = St + TA_BYTES;
        const uint32_t B0 = St + 2*TA_BYTES;
        const uint32_t B1 = B0 + TB_BYTES;

        #pragma unroll
        for (int ks = 0; ks < 4; ks++) {
            const int kc = ks*16 + khalf;
            uint32_t a0[4], a1f[4];
            uint32_t b0[3][4], b1f[3][4];
            LDSM4(a0,  ldsm_addr(A0, wm + arow, kc));
            LDSM4(a1f, ldsm_addr(A1, wm + arow, kc));
            #pragma unroll
            for (int t = 0; t < 3; t++) {
                int row = wn + t*16 + arow;
                LDSM4(b0[t],  ldsm_addr(B0, row, kc));
                LDSM4(b1f[t], ldsm_addr(B1, row, kc));
            }
            #pragma unroll
            for (int t = 0; t < 3; t++)
                #pragma unroll
                for (int s = 0; s < 2; s++) {
                    const int n8 = t*2 + s;
                    // main term: zero-C MMA + RN register accumulate
                    float dt[4];
                    MMA16816_Z(dt, a0, b0[t][s], b0[t][2+s]);
                    acc0[n8][0] += dt[0];
                    acc0[n8][1] += dt[1];
                    acc0[n8][2] += dt[2];
                    acc0[n8][3] += dt[3];
                    // 2^-11-scaled cross terms (chained; bias negligible)
                    MMA16816(acc1[n8], a0,  b1f[t][s], b1f[t][2+s]);
                    MMA16816(acc1[n8], a1f, b0[t][s],  b0[t][2+s]);
                }
        }
        __syncthreads();
    }

    // ---- epilogue part 1: gh -> smem exchange ----
    float* ghs = (float*)smc;   // 64 x GHS_PITCH fp32 (25.6KB, reuse stage)
    {
        int erow = wm + (lane >> 2);
        #pragma unroll
        for (int n8 = 0; n8 < 6; n8++) {
            int col = wn + n8*8 + (lane & 3)*2;
            ghs[erow*GHS_PITCH + col]       = acc0[n8][0] + acc1[n8][0]*P1;
            ghs[erow*GHS_PITCH + col + 1]   = acc0[n8][1] + acc1[n8][1]*P1;
            ghs[(erow+8)*GHS_PITCH + col]     = acc0[n8][2] + acc1[n8][2]*P1;
            ghs[(erow+8)*GHS_PITCH + col + 1] = acc0[n8][3] + acc1[n8][3]*P1;
        }
    }
    __syncthreads();

    // ---- epilogue part 2: gate math + h/plane writeback ----
    const float* __restrict__ G  = table_sel ? g_Gtrg : g_Gsrc;
    const int* __restrict__ tokp = ext_tok ? ext_tok : g_tok;
    #pragma unroll
    for (int q = 0; q < 8; q++) {
        int idx = tid + 256*q;           // 0..2047
        int row = idx >> 5;              // 0..63
        int hc  = idx & 31;              // 0..31
        int col  = nt*32 + hc;           // global h-col
        int rowg = mt*64 + row;          // global batch row
        int tok = tokp[rowg * tok_stride];
        const float* Grow = G + (size_t)tok*G3;

        float vr = ghs[row*GHS_PITCH + hc];
        float vz = ghs[row*GHS_PITCH + 32 + hc];
        float vn = ghs[row*GHS_PITCH + 64 + hc];
        float gr = vr + bhh[col];
        float gz = vz + bhh[HH + col];
        float gn = vn + bhh[2*HH + col];
        float r = 1.0f / (1.0f + expf(-(Grow[col]      + gr)));
        float z = 1.0f / (1.0f + expf(-(Grow[HH + col] + gz)));
        float n = tanhf(Grow[2*HH + col] + r * gn);
        float hp = g_h[pin][rowg*HH + col];
        float ho = (1.0f - z)*n + z*hp;

        g_h[pin ^ 1][rowg*HH + col] = ho;
        __half h0, h1;
        split2(ho, h0, h1);
        size_t pos = ((size_t)(rowg >> 6)*NCHUNK + (col >> 6))*TA_HALFS
                   + sw_half(rowg & 63, col & 63);
        g_hP[pin ^ 1][0][pos] = h0;
        g_hP[pin ^ 1][1][pos] = h1;
    }
}

// ================= decoder pred GEMM (split-K SIMT, fp32) =================
#define PBM 32
#define PBK 16
__global__ __launch_bounds__(256, 1)
void pred_part(int pcur, const float* __restrict__ fcW)
{
    const float* __restrict__ h = g_h[pcur];
    __shared__ float As[PBK][PBM+4];
    __shared__ float Bs[PBK][VV+4];

    const int row0 = blockIdx.x * PBM;
    const int k0   = blockIdx.y * (HH/8);
    const int tx = threadIdx.x, ty = threadIdx.y;
    const int tid = ty*32 + tx;

    float acc[4][4];
    #pragma unroll
    for (int i = 0; i < 4; i++)
        #pragma unroll
        for (int j = 0; j < 4; j++) acc[i][j] = 0.0f;

    for (int kt = 0; kt < HH/8; kt += PBK) {
        if (tid < 128) {
            int ar = tid >> 2;
            int ak = (tid & 3) << 2;
            float4 av = *(const float4*)&h[(row0+ar)*HH + k0 + kt + ak];
            As[ak+0][ar] = av.x; As[ak+1][ar] = av.y;
            As[ak+2][ar] = av.z; As[ak+3][ar] = av.w;
        }
        #pragma unroll
        for (int l = 0; l < 2; l++) {
            int t2 = l*256 + tid;
            int bc = t2 >> 2;
            int bk = (t2 & 3) << 2;
            float4 bv = *(const float4*)&fcW[bc*HH + k0 + kt + bk];
            Bs[bk+0][bc] = bv.x; Bs[bk+1][bc] = bv.y;
            Bs[bk+2][bc] = bv.z; Bs[bk+3][bc] = bv.w;
        }
        __syncthreads();
        #pragma unroll
        for (int kk = 0; kk < PBK; kk++) {
            float4 a = *(const float4*)&As[kk][ty*4];
            float4 b = *(const float4*)&Bs[kk][tx*4];
            float av[4] = {a.x,a.y,a.z,a.w};
            float bv[4] = {b.x,b.y,b.z,b.w};
            #pragma unroll
            for (int i = 0; i < 4; i++)
                #pragma unroll
                for (int j = 0; j < 4; j++) acc[i][j] += av[i]*bv[j];
        }
        __syncthreads();
    }
    float* dst = g_pred_part[blockIdx.y];
    #pragma unroll
    for (int i = 0; i < 4; i++)
        #pragma unroll
        for (int j = 0; j < 4; j++)
            dst[(row0 + ty*4 + i)*VV + tx*4 + j] = acc[i][j];
}

// ================= reduce + bias + out + argmax -> next token =================
__global__ void argmax_write(float* __restrict__ out,
                             const float* __restrict__ fcb,
                             const int* __restrict__ trg,
                             const void* __restrict__ tfr,
                             int t_out)
{
    int b = blockIdx.x;
    int v = threadIdx.x;
    float acc = fcb[v];
    #pragma unroll
    for (int p = 0; p < 8; p++) acc += g_pred_part[p][b*VV + v];
    out[b*(TT*VV) + t_out*VV + v] = acc;

    __shared__ float sval[128];
    __shared__ int   sidx[128];
    sval[v] = acc; sidx[v] = v;
    __syncthreads();
    for (int s = 64; s > 0; s >>= 1) {
        if (v < s) {
            if (sval[v+s] > sval[v] ||
                (sval[v+s] == sval[v] && sidx[v+s] < sidx[v])) {
                sval[v] = sval[v+s]; sidx[v] = sidx[v+s];
            }
        }
        __syncthreads();
    }
    if (v == 0) {
        int   ti  = ((const int*)tfr)[0];
        float tfv = ((const float*)tfr)[0];
        bool tf = (ti > 0) || (tfv > 0.0f);
        g_tok[b] = tf ? trg[b*TT + t_out] : sidx[0];
    }
}

// ================= host =================
extern "C" void kernel_launch(void* const* d_in, const int* in_sizes, int n_in,
                              void* d_out, int out_size)
{
    const int*   src     = (const int*)  d_in[0];
    const int*   trg     = (const int*)  d_in[1];
    const float* emb_src = (const float*)d_in[2];
    const float* emb_trg = (const float*)d_in[3];
    const float* enc_Wih = (const float*)d_in[4];
    const float* enc_Whh = (const float*)d_in[5];
    const float* enc_bih = (const float*)d_in[6];
    const float* enc_bhh = (const float*)d_in[7];
    const float* dec_Wih = (const float*)d_in[8];
    const float* dec_Whh = (const float*)d_in[9];
    const float* dec_bih = (const float*)d_in[10];
    const float* dec_bhh = (const float*)d_in[11];
    const float* fc_W    = (const float*)d_in[12];
    const float* fc_b    = (const float*)d_in[13];
    const void*  tfr     =               d_in[14];
    float* out = (float*)d_out;

    cudaFuncSetAttribute(gru_gemm, cudaFuncAttributeMaxDynamicSharedMemorySize, SMEM_DYN);

    build_tables<<<(2*VV*G3)/256, 256>>>(emb_src, enc_Wih, enc_bih,
                                         emb_trg, dec_Wih, dec_bih);
    build_wsplit<<<(2*G3*HH)/256, 256>>>(enc_Whh, dec_Whh);
    init_kernel<<<(NB*HH)/256, 256>>>(out, trg);

    dim3 ggrid(HH/HCOL, NB/BM);   // (32, 8) = 256 blocks
    int p = 0;

    // encoder (gate fused into the GEMM)
    for (int t = 0; t < SS; t++) {
        gru_gemm<<<ggrid, 256, SMEM_DYN>>>(p, 0, 0, src + t, SS, enc_bhh);
        p ^= 1;
    }
    // decoder
    dim3 pgrid(NB/PBM, 8);
    dim3 pblk(32, 8);
    for (int t = 0; t < TT-1; t++) {
        gru_gemm<<<ggrid, 256, SMEM_DYN>>>(p, 1, 1, (const int*)nullptr, 1, dec_bhh);
        p ^= 1;
        pred_part<<<pgrid, pblk>>>(p, fc_W);
        argmax_write<<<NB, VV>>>(out, fc_b, trg, tfr, t + 1);
    }
}

// round 12
// speedup vs baseline: 2.3768x; 1.0231x over previous
#include <cuda_runtime.h>
#include <cuda_fp16.h>
#include <math.h>
#include <stdint.h>

#define NB 512
#define SS 128
#define TT 128
#define EE 128
#define HH 1024
#define VV 128
#define G3 (3*HH)

#define BM 128                     // batch rows per block
#define HCOL 32                    // h-columns per block
#define BNR 96                     // B rows per block (3 gates x 32)
#define KS 64
#define NCHUNK (HH/KS)             // 16
#define THREADS 512
#define TA_HALFS (BM*KS)           // 8192 per plane
#define TB_HALFS (BNR*KS)          // 6144 per plane
#define TA_BYTES (TA_HALFS*2)      // 16384
#define TB_BYTES (TB_HALFS*2)      // 12288
#define STAGE_BYTES (2*TA_BYTES + 2*TB_BYTES)   // 57344
#define NSTAGE 3
#define SMEM_DYN (NSTAGE*STAGE_BYTES)           // 172032
#define GHS_PITCH 100              // fp32 pitch for epilogue exchange

#define P1 (1.0f/2048.0f)
#define S1 2048.0f

// ================= device scratch =================
__device__ float g_h[2][NB*HH];                           // fp32 hidden master
__device__ __align__(16) __half g_hP[2][2][NB*HH];        // h planes, 128x64 A-tile layout
__device__ __align__(16) __half g_WP[2][2][(size_t)G3*HH];// Whh planes, gate-interleaved B-tiles
__device__ float g_Gsrc[VV*G3];
__device__ float g_Gtrg[VV*G3];
__device__ int   g_tok[NB];
__device__ float g_pred_part[8][NB*VV];

// ================= PTX helpers (portable) =================
__device__ __forceinline__ uint32_t smem_u32(const void* p) {
    uint32_t a;
    asm("{ .reg .u64 t; cvta.to.shared.u64 t, %1; cvt.u32.u64 %0, t; }" : "=r"(a) : "l"(p));
    return a;
}
#define CP16(sm, gp) \
    asm volatile("cp.async.cg.shared.global [%0], [%1], 16;" :: "r"(sm), "l"(gp) : "memory")
#define CP_COMMIT() asm volatile("cp.async.commit_group;" ::: "memory")
#define CP_WAIT1()  asm volatile("cp.async.wait_group 1;" ::: "memory")
#define CP_WAIT0()  asm volatile("cp.async.wait_group 0;" ::: "memory")
#define LDSM4(r, a) \
    asm volatile("ldmatrix.sync.aligned.m8n8.x4.shared.b16 {%0,%1,%2,%3}, [%4];" \
        : "=r"((r)[0]),"=r"((r)[1]),"=r"((r)[2]),"=r"((r)[3]) : "r"(a))
// chained MMA (in-HMMA accumulate; only for the 2^-11-scaled cross terms)
#define MMA16816(d, a, b0, b1) \
    asm volatile("mma.sync.aligned.m16n8k16.row.col.f32.f16.f16.f32 " \
        "{%0,%1,%2,%3}, {%4,%5,%6,%7}, {%8,%9}, {%0,%1,%2,%3};" \
        : "+f"((d)[0]),"+f"((d)[1]),"+f"((d)[2]),"+f"((d)[3]) \
        : "r"((a)[0]),"r"((a)[1]),"r"((a)[2]),"r"((a)[3]), "r"(b0),"r"(b1))
// zero-C MMA: fresh outputs, no in-HMMA chaining (main term, RN reg accumulate)
#define MMA16816_Z(d, a, b0, b1) \
    asm volatile("mma.sync.aligned.m16n8k16.row.col.f32.f16.f16.f32 " \
        "{%0,%1,%2,%3}, {%4,%5,%6,%7}, {%8,%9}, {%10,%10,%10,%10};" \
        : "=f"((d)[0]),"=f"((d)[1]),"=f"((d)[2]),"=f"((d)[3]) \
        : "r"((a)[0]),"r"((a)[1]),"r"((a)[2]),"r"((a)[3]), "r"(b0),"r"(b1), "f"(0.0f))

// swizzled half index within a tile (row pitch 128B; 16B chunk ^= row&7)
__device__ __forceinline__ int sw_half(int r, int c) {
    return r*64 + (((c>>3) ^ (r&7))<<3) + (c&7);
}
__device__ __forceinline__ uint32_t ldsm_addr(uint32_t tbase, int row, int kc) {
    return tbase + row*128 + ((((kc>>3) ^ (row&7))&7)<<4);
}
// exact 2-plane fp16 split (lo scaled by 2048 into normal range)
__device__ __forceinline__ void split2(float v, __half& h0, __half& h1) {
    h0 = __float2half(v);
    float r1 = v - __half2float(h0);
    h1 = __float2half(r1 * S1);
}

// ================= build: gi tables =================
__global__ void build_tables(const float* __restrict__ emb_src,
                             const float* __restrict__ enc_Wih,
                             const float* __restrict__ enc_bih,
                             const float* __restrict__ emb_trg,
                             const float* __restrict__ dec_Wih,
                             const float* __restrict__ dec_bih)
{
    int idx = blockIdx.x * blockDim.x + threadIdx.x;
    int which = idx / (VV*G3);
    int rem   = idx % (VV*G3);
    int v = rem / G3;
    int c = rem % G3;
    const float* emb = which ? emb_trg : emb_src;
    const float* W   = which ? dec_Wih : enc_Wih;
    const float* bi  = which ? dec_bih : enc_bih;
    float s = bi[c];
    if (v != 0) {
        const float* e = emb + v*EE;
        const float* w = W + c*EE;
        #pragma unroll 8
        for (int k = 0; k < EE; k++) s += e[k]*w[k];
    }
    float* G = which ? g_Gtrg : g_Gsrc;
    G[v*G3 + c] = s;
}

// ===== build: Whh 2-plane split, gate-interleaved B-tile layout =====
__global__ void build_wsplit(const float* __restrict__ enc_Whh,
                             const float* __restrict__ dec_Whh)
{
    int idx = blockIdx.x * blockDim.x + threadIdx.x;   // 2*3072*1024
    int dir = idx / (G3*HH);
    int rem = idx % (G3*HH);
    int n = rem / HH;          // Whh row: gate*1024 + h
    int k = rem % HH;
    const float* W = dir ? dec_Whh : enc_Whh;
    float v = W[n*HH + k];
    __half h0, h1;
    split2(v, h0, h1);
    int gate = n >> 10;
    int h    = n & 1023;
    int nt   = h >> 5;
    int trow = gate*32 + (h & 31);
    size_t pos = ((size_t)nt*NCHUNK + (k >> 6))*TB_HALFS + sw_half(trow, k & 63);
    g_WP[dir][0][pos] = h0;
    g_WP[dir][1][pos] = h1;
}

// ================= init =================
__global__ void init_kernel(float* __restrict__ out, const int* __restrict__ trg)
{
    int i = blockIdx.x * blockDim.x + threadIdx.x;
    if (i < NB*HH) {
        g_h[0][i] = 0.0f;
        g_hP[0][0][i] = __float2half(0.0f);
        g_hP[0][1][i] = __float2half(0.0f);
    }
    if (i < NB*VV) {
        int b = i / VV, v = i % VV;
        out[b*(TT*VV) + v] = 0.0f;
    }
    if (i < NB) g_tok[i] = trg[i*TT];
}

// ====== fused GRU step: gate-triple tensor GEMM + gate epilogue ======
// grid (32, 4): x = h-col tile, y = m-tile (512/128). 512 threads, 1 CTA/SM.
// 16 warps as 8m x 2n, warp tile 16x48 (identical inner math to R11).
// 3-stage cp.async pipeline, one __syncthreads per chunk.
__global__ __launch_bounds__(THREADS, 1)
void gru_gemm(int pin, int dir, int table_sel,
              const int* __restrict__ ext_tok, int tok_stride,
              const float* __restrict__ bhh)
{
    extern __shared__ char smc[];
    const uint32_t sbase = smem_u32(smc);
    const int tid  = threadIdx.x;
    const int wid  = tid >> 5;
    const int lane = tid & 31;
    const int nt = blockIdx.x;           // h-col tile
    const int mt = blockIdx.y;           // m tile
    const int wm = (wid >> 1) * 16;      // warp m offset: 0..112
    const int wn = (wid & 1) * 48;       // warp B-row offset: 0/48

    const char* gA0 = (const char*)g_hP[pin][0] + (size_t)mt*NCHUNK*TA_BYTES;
    const char* gA1 = (const char*)g_hP[pin][1] + (size_t)mt*NCHUNK*TA_BYTES;
    const char* gB0 = (const char*)g_WP[dir][0] + (size_t)nt*NCHUNK*TB_BYTES;
    const char* gB1 = (const char*)g_WP[dir][1] + (size_t)nt*NCHUNK*TB_BYTES;

    float acc0[6][4], acc1[6][4];
    #pragma unroll
    for (int j = 0; j < 6; j++)
        #pragma unroll
        for (int q = 0; q < 4; q++) { acc0[j][q] = 0.0f; acc1[j][q] = 0.0f; }

    // ---- cp.async issue helper (manually inlined twice) ----
    // A: 2048 lines of 16B (2 planes x 1024); B: 1536 lines (2 planes x 768)
    #define ISSUE_CHUNK(cc, buf) do {                                        \
        uint32_t sb = sbase + (buf)*STAGE_BYTES;                             \
        size_t goA = (size_t)(cc) * TA_BYTES;                                \
        size_t goB = (size_t)(cc) * TB_BYTES;                                \
        _Pragma("unroll")                                                    \
        for (int j = 0; j < 4; j++) {                                        \
            int u = tid + THREADS*j;             /* 0..2047 */               \
            int pl = u >> 10;                                                \
            int ln = u & 1023;                                               \
            const char* src = (pl ? gA1 : gA0) + goA + ln*16;                \
            CP16(sb + pl*TA_BYTES + ln*16, src);                             \
        }                                                                    \
        _Pragma("unroll")                                                    \
        for (int j = 0; j < 3; j++) {                                        \
            int u = tid + THREADS*j;             /* 0..1535 */               \
            int pl = (u >= 768);                                             \
            int ln = u - pl*768;                                             \
            const char* src = (pl ? gB1 : gB0) + goB + ln*16;                \
            CP16(sb + 2*TA_BYTES + pl*TB_BYTES + ln*16, src);                \
        }                                                                    \
        CP_COMMIT();                                                         \
    } while (0)

    // prologue: stages 0 and 1
    ISSUE_CHUNK(0, 0);
    ISSUE_CHUNK(1, 1);

    const int arow  = lane & 15;
    const int khalf = (lane >> 4) * 8;

    int rbuf = 0;                        // c % 3
    for (int c = 0; c < NCHUNK; c++) {
        // wait for stage c (outstanding newest: {c, c+1} except last)
        if (c < NCHUNK-1) { CP_WAIT1(); } else { CP_WAIT0(); }
        __syncthreads();

        const uint32_t St = sbase + rbuf*STAGE_BYTES;
        const uint32_t A0 = St;
        const uint32_t A1 = St + TA_BYTES;
        const uint32_t B0 = St + 2*TA_BYTES;
        const uint32_t B1 = B0 + TB_BYTES;

        #pragma unroll
        for (int ks = 0; ks < 4; ks++) {
            const int kc = ks*16 + khalf;
            uint32_t a0[4], a1f[4];
            uint32_t b0[3][4], b1f[3][4];
            LDSM4(a0,  ldsm_addr(A0, wm + arow, kc));
            LDSM4(a1f, ldsm_addr(A1, wm + arow, kc));
            #pragma unroll
            for (int t = 0; t < 3; t++) {
                int row = wn + t*16 + arow;
                LDSM4(b0[t],  ldsm_addr(B0, row, kc));
                LDSM4(b1f[t], ldsm_addr(B1, row, kc));
            }
            #pragma unroll
            for (int t = 0; t < 3; t++)
                #pragma unroll
                for (int s = 0; s < 2; s++) {
                    const int n8 = t*2 + s;
                    // main term: zero-C MMA + RN register accumulate
                    float dt[4];
                    MMA16816_Z(dt, a0, b0[t][s], b0[t][2+s]);
                    acc0[n8][0] += dt[0];
                    acc0[n8][1] += dt[1];
                    acc0[n8][2] += dt[2];
                    acc0[n8][3] += dt[3];
                    // 2^-11-scaled cross terms (chained; bias negligible)
                    MMA16816(acc1[n8], a0,  b1f[t][s], b1f[t][2+s]);
                    MMA16816(acc1[n8], a1f, b0[t][s],  b0[t][2+s]);
                }
        }

        // issue stage c+2 into buffer (c+2)%3 (safe: all warps passed this
        // chunk's barrier, so readers of that buffer — chunk c-1 — are done)
        if (c + 2 < NCHUNK) {
            int wbuf = rbuf + 2; if (wbuf >= 3) wbuf -= 3;
            ISSUE_CHUNK(c+2, wbuf);
        }
        rbuf = (rbuf == 2) ? 0 : rbuf + 1;
    }
    #undef ISSUE_CHUNK

    // ---- epilogue part 1: gh -> smem exchange ----
    __syncthreads();                     // last stage readers done before reuse
    float* ghs = (float*)smc;            // 128 x GHS_PITCH fp32 (51.2KB)
    {
        int erow = wm + (lane >> 2);
        #pragma unroll
        for (int n8 = 0; n8 < 6; n8++) {
            int col = wn + n8*8 + (lane & 3)*2;
            ghs[erow*GHS_PITCH + col]         = acc0[n8][0] + acc1[n8][0]*P1;
            ghs[erow*GHS_PITCH + col + 1]     = acc0[n8][1] + acc1[n8][1]*P1;
            ghs[(erow+8)*GHS_PITCH + col]     = acc0[n8][2] + acc1[n8][2]*P1;
            ghs[(erow+8)*GHS_PITCH + col + 1] = acc0[n8][3] + acc1[n8][3]*P1;
        }
    }
    __syncthreads();

    // ---- epilogue part 2: gate math + h/plane writeback ----
    const float* __restrict__ G  = table_sel ? g_Gtrg : g_Gsrc;
    const int* __restrict__ tokp = ext_tok ? ext_tok : g_tok;
    #pragma unroll
    for (int q = 0; q < 8; q++) {
        int idx = tid + THREADS*q;       // 0..4095
        int row = idx >> 5;              // 0..127
        int hc  = idx & 31;              // 0..31
        int col  = nt*32 + hc;           // global h-col
        int rowg = mt*BM + row;          // global batch row
        int tok = tokp[rowg * tok_stride];
        const float* Grow = G + (size_t)tok*G3;

        float vr = ghs[row*GHS_PITCH + hc];
        float vz = ghs[row*GHS_PITCH + 32 + hc];
        float vn = ghs[row*GHS_PITCH + 64 + hc];
        float gr = vr + bhh[col];
        float gz = vz + bhh[HH + col];
        float gn = vn + bhh[2*HH + col];
        float r = 1.0f / (1.0f + expf(-(Grow[col]      + gr)));
        float z = 1.0f / (1.0f + expf(-(Grow[HH + col] + gz)));
        float n = tanhf(Grow[2*HH + col] + r * gn);
        float hp = g_h[pin][rowg*HH + col];
        float ho = (1.0f - z)*n + z*hp;

        g_h[pin ^ 1][rowg*HH + col] = ho;
        __half h0, h1;
        split2(ho, h0, h1);
        size_t pos = ((size_t)(rowg >> 7)*NCHUNK + (col >> 6))*TA_HALFS
                   + sw_half(rowg & 127, col & 63);
        g_hP[pin ^ 1][0][pos] = h0;
        g_hP[pin ^ 1][1][pos] = h1;
    }
}

// ================= decoder pred GEMM (split-K SIMT, fp32) =================
#define PBM 32
#define PBK 16
__global__ __launch_bounds__(256, 1)
void pred_part(int pcur, const float* __restrict__ fcW)
{
    const float* __restrict__ h = g_h[pcur];
    __shared__ float As[PBK][PBM+4];
    __shared__ float Bs[PBK][VV+4];

    const int row0 = blockIdx.x * PBM;
    const int k0   = blockIdx.y * (HH/8);
    const int tx = threadIdx.x, ty = threadIdx.y;
    const int tid = ty*32 + tx;

    float acc[4][4];
    #pragma unroll
    for (int i = 0; i < 4; i++)
        #pragma unroll
        for (int j = 0; j < 4; j++) acc[i][j] = 0.0f;

    for (int kt = 0; kt < HH/8; kt += PBK) {
        if (tid < 128) {
            int ar = tid >> 2;
            int ak = (tid & 3) << 2;
            float4 av = *(const float4*)&h[(row0+ar)*HH + k0 + kt + ak];
            As[ak+0][ar] = av.x; As[ak+1][ar] = av.y;
            As[ak+2][ar] = av.z; As[ak+3][ar] = av.w;
        }
        #pragma unroll
        for (int l = 0; l < 2; l++) {
            int t2 = l*256 + tid;
            int bc = t2 >> 2;
            int bk = (t2 & 3) << 2;
            float4 bv = *(const float4*)&fcW[bc*HH + k0 + kt + bk];
            Bs[bk+0][bc] = bv.x; Bs[bk+1][bc] = bv.y;
            Bs[bk+2][bc] = bv.z; Bs[bk+3][bc] = bv.w;
        }
        __syncthreads();
        #pragma unroll
        for (int kk = 0; kk < PBK; kk++) {
            float4 a = *(const float4*)&As[kk][ty*4];
            float4 b = *(const float4*)&Bs[kk][tx*4];
            float av[4] = {a.x,a.y,a.z,a.w};
            float bv[4] = {b.x,b.y,b.z,b.w};
            #pragma unroll
            for (int i = 0; i < 4; i++)
                #pragma unroll
                for (int j = 0; j < 4; j++) acc[i][j] += av[i]*bv[j];
        }
        __syncthreads();
    }
    float* dst = g_pred_part[blockIdx.y];
    #pragma unroll
    for (int i = 0; i < 4; i++)
        #pragma unroll
        for (int j = 0; j < 4; j++)
            dst[(row0 + ty*4 + i)*VV + tx*4 + j] = acc[i][j];
}

// ================= reduce + bias + out + argmax -> next token =================
__global__ void argmax_write(float* __restrict__ out,
                             const float* __restrict__ fcb,
                             const int* __restrict__ trg,
                             const void* __restrict__ tfr,
                             int t_out)
{
    int b = blockIdx.x;
    int v = threadIdx.x;
    float acc = fcb[v];
    #pragma unroll
    for (int p = 0; p < 8; p++) acc += g_pred_part[p][b*VV + v];
    out[b*(TT*VV) + t_out*VV + v] = acc;

    __shared__ float sval[128];
    __shared__ int   sidx[128];
    sval[v] = acc; sidx[v] = v;
    __syncthreads();
    for (int s = 64; s > 0; s >>= 1) {
        if (v < s) {
            if (sval[v+s] > sval[v] ||
                (sval[v+s] == sval[v] && sidx[v+s] < sidx[v])) {
                sval[v] = sval[v+s]; sidx[v] = sidx[v+s];
            }
        }
        __syncthreads();
    }
    if (v == 0) {
        int   ti  = ((const int*)tfr)[0];
        float tfv = ((const float*)tfr)[0];
        bool tf = (ti > 0) || (tfv > 0.0f);
        g_tok[b] = tf ? trg[b*TT + t_out] : sidx[0];
    }
}

// ================= host =================
extern "C" void kernel_launch(void* const* d_in, const int* in_sizes, int n_in,
                              void* d_out, int out_size)
{
    const int*   src     = (const int*)  d_in[0];
    const int*   trg     = (const int*)  d_in[1];
    const float* emb_src = (const float*)d_in[2];
    const float* emb_trg = (const float*)d_in[3];
    const float* enc_Wih = (const float*)d_in[4];
    const float* enc_Whh = (const float*)d_in[5];
    const float* enc_bih = (const float*)d_in[6];
    const float* enc_bhh = (const float*)d_in[7];
    const float* dec_Wih = (const float*)d_in[8];
    const float* dec_Whh = (const float*)d_in[9];
    const float* dec_bih = (const float*)d_in[10];
    const float* dec_bhh = (const float*)d_in[11];
    const float* fc_W    = (const float*)d_in[12];
    const float* fc_b    = (const float*)d_in[13];
    const void*  tfr     =               d_in[14];
    float* out = (float*)d_out;

    cudaFuncSetAttribute(gru_gemm, cudaFuncAttributeMaxDynamicSharedMemorySize, SMEM_DYN);

    build_tables<<<(2*VV*G3)/256, 256>>>(emb_src, enc_Wih, enc_bih,
                                         emb_trg, dec_Wih, dec_bih);
    build_wsplit<<<(2*G3*HH)/256, 256>>>(enc_Whh, dec_Whh);
    init_kernel<<<(NB*HH)/256, 256>>>(out, trg);

    dim3 ggrid(HH/HCOL, NB/BM);   // (32, 4) = 128 blocks
    int p = 0;

    // encoder (gate fused into the GEMM)
    for (int t = 0; t < SS; t++) {
        gru_gemm<<<ggrid, THREADS, SMEM_DYN>>>(p, 0, 0, src + t, SS, enc_bhh);
        p ^= 1;
    }
    // decoder
    dim3 pgrid(NB/PBM, 8);
    dim3 pblk(32, 8);
    for (int t = 0; t < TT-1; t++) {
        gru_gemm<<<ggrid, THREADS, SMEM_DYN>>>(p, 1, 1, (const int*)nullptr, 1, dec_bhh);
        p ^= 1;
        pred_part<<<pgrid, pblk>>>(p, fc_W);
        argmax_write<<<NB, VV>>>(out, fc_b, trg, tfr, t + 1);
    }
}